// round 5
// baseline (speedup 1.0000x reference)
#include <cuda_runtime.h>

// CoExCostVolume: cost[b,d,h,w] = sum_c x[b,c,h,w]*y[b,c,h,w-d], zero for w<d.
// B=8, C=96, H=128, W=416, D=49.
//
// Grid 2048 = (b, h, half-row of 208 w). 224 threads = 7 warps; warp wid owns
// disparities d in [7*wid, 7*wid+7), lane L (<26) owns w in [8L, 8L+8).
// Warp-uniform d0 => every smem load offset is a compile-time immediate
// (accum<W> specializations). x: +2/8 skew, LDS.64 conflict-free; y: +1/8 skew,
// scalar LDS conflict-free. cp.async 3-buffer pipeline, 12 chunks of 8 channels.
// 3 CTAs/SM (52.6KB smem, <=97 regs via launch_bounds).

#define B_DIM 8
#define C_DIM 96
#define H_DIM 128
#define W_DIM 416
#define D_DIM 49
#define HW (H_DIM * W_DIM)
#define HALFW 208

#define CC 8
#define NC 12
#define NBUF 3
#define XSTRIDE 260           // >= sidxx(207)+1 = 258, even
#define YSTRIDE 288           // >= SY(255)+1 = 287, even
#define XSZ (CC * XSTRIDE)    // 2080
#define YSZ (CC * YSTRIDE)    // 2304
#define BUFSZ (XSZ + YSZ)     // 4384 floats
#define NTHREADS 224
#define SMEM_BYTES (NBUF * BUFSZ * 4)   // 52608

typedef unsigned long long ull;

__host__ __device__ constexpr int SY(int p) { return p + (p >> 3); }   // +1/8 skew
__device__ __forceinline__ int sidxx(int p) { return p + ((p >> 3) << 1); } // +2/8

__device__ __forceinline__ void cp8(float* dst_smem, const float* src) {
    unsigned s = (unsigned)__cvta_generic_to_shared(dst_smem);
    asm volatile("cp.async.ca.shared.global [%0], [%1], 8;\n" ::"r"(s), "l"(src));
}
__device__ __forceinline__ void cp4(float* dst_smem, const float* src) {
    unsigned s = (unsigned)__cvta_generic_to_shared(dst_smem);
    asm volatile("cp.async.ca.shared.global [%0], [%1], 4;\n" ::"r"(s), "l"(src));
}
__device__ __forceinline__ ull pk(float lo, float hi) {
    ull r; asm("mov.b64 %0, {%1, %2};" : "=l"(r) : "f"(lo), "f"(hi)); return r;
}
__device__ __forceinline__ void fma2(ull& d, ull a, ull b) {
    asm("fma.rn.f32x2 %0, %1, %2, %0;" : "+l"(d) : "l"(a), "l"(b));
}
__device__ __forceinline__ float2 upk(ull p) {
    float2 v; asm("mov.b64 {%0, %1}, %2;" : "=f"(v.x), "=f"(v.y) : "l"(p)); return v;
}

// Per-warp-specialized accumulation over one 8-channel chunk.
// xB = xs + 10*L floats (skewed x base), yB = ys + 9*L floats (skewed y base).
// All offsets below are compile-time constants.
template <int W>
__device__ __forceinline__ void accum(const float* __restrict__ xB,
                                      const float* __restrict__ yB,
                                      ull* __restrict__ acc) {
    constexpr int Q = 42 - 7 * W;  // y window base coord minus 8L (multiple of 1)
#pragma unroll
    for (int c = 0; c < CC; c++) {
        const float* xr = xB + c * XSTRIDE;
        const float* yr = yB + c * YSTRIDE;
        float2 xp[4];
#pragma unroll
        for (int j = 0; j < 4; j++)
            xp[j] = *reinterpret_cast<const float2*>(xr + 2 * j);
        float yv[14];
#pragma unroll
        for (int t = 0; t < 14; t++) yv[t] = yr[SY(Q + t)];

        ull px[4];
#pragma unroll
        for (int j = 0; j < 4; j++) px[j] = pk(xp[j].x, xp[j].y);
        ull py[13];
#pragma unroll
        for (int t = 0; t < 13; t++) py[t] = pk(yv[t], yv[t + 1]);

#pragma unroll
        for (int i = 0; i < 7; i++)
#pragma unroll
            for (int j = 0; j < 4; j++)
                fma2(acc[i * 4 + j], px[j], py[2 * j + 6 - i]);
    }
}

__global__ void __launch_bounds__(NTHREADS, 3)
coex_cost_kernel(const float* __restrict__ x,
                 const float* __restrict__ y,
                 float* __restrict__ out) {
    extern __shared__ float sm[];

    const int bid = blockIdx.x;
    const int half = bid & 1;
    const int h = (bid >> 1) & 127;
    const int b = bid >> 8;
    const int W0 = half * HALFW;

    const int tid = threadIdx.x;
    const int wid = tid >> 5;        // 0..6 : d-group (warp-uniform)
    const int lane = tid & 31;       // 0..25 active for compute/stores

    // global bases for this (b,h,half)
    const long rowb = ((long)(b * C_DIM) * H_DIM + h) * W_DIM;
    const long gx = rowb + W0;        // x stage base
    const long gy = rowb + W0 - 48;   // y stage base (coord p in [0,256))
    const int pmin = half ? 0 : 48;   // y coords < 48 are zero pad for half 0

    // ---- zero y left-pad (half 0 only), all buffers, once ----
    if (half == 0) {
        for (int i = tid; i < NBUF * CC * 48; i += NTHREADS) {
            int buf = i / (CC * 48);
            int r = i - buf * (CC * 48);
            int c = r / 48;
            int p = r - c * 48;
            sm[buf * BUFSZ + XSZ + c * YSTRIDE + SY(p)] = 0.0f;
        }
    }

    // ---- staging ----
    auto stage = [&](int k) {
        const long co = (long)k * CC * HW;
        float* xs = sm + (k % NBUF) * BUFSZ;
        float* ys = xs + XSZ;
        // x: CC*104 float2
#pragma unroll 1
        for (int idx = tid; idx < CC * 104; idx += NTHREADS) {
            int c = idx / 104;
            int w = (idx - c * 104) * 2;
            cp8(xs + c * XSTRIDE + sidxx(w), x + gx + co + (long)c * HW + w);
        }
        // y: CC*256 floats (coords [pmin,256))
#pragma unroll 1
        for (int idx = tid; idx < CC * 256; idx += NTHREADS) {
            int c = idx >> 8;
            int p = idx & 255;
            if (p >= pmin)
                cp4(ys + c * YSTRIDE + SY(p), y + gy + co + (long)c * HW + p);
        }
    };

    ull acc[28];
#pragma unroll
    for (int i = 0; i < 28; i++) acc[i] = 0ull;

    const int xboff = 10 * lane;      // sidxx(8*lane)
    const int yboff = 9 * lane;       // skew part of sidxy(8*lane + q)

    stage(0); asm volatile("cp.async.commit_group;\n");
    stage(1); asm volatile("cp.async.commit_group;\n");

#pragma unroll 1
    for (int k = 0; k < NC; k++) {
        if (k < NC - 1) asm volatile("cp.async.wait_group 1;\n" ::: "memory");
        else            asm volatile("cp.async.wait_group 0;\n" ::: "memory");
        __syncthreads();

        if (k + 2 < NC) {
            stage(k + 2);
            asm volatile("cp.async.commit_group;\n");
        }

        const float* buf = sm + (k % NBUF) * BUFSZ;
        const float* xB = buf + xboff;
        const float* yB = buf + XSZ + yboff;
        if (lane < 26) {
            switch (wid) {
                case 0: accum<0>(xB, yB, acc); break;
                case 1: accum<1>(xB, yB, acc); break;
                case 2: accum<2>(xB, yB, acc); break;
                case 3: accum<3>(xB, yB, acc); break;
                case 4: accum<4>(xB, yB, acc); break;
                case 5: accum<5>(xB, yB, acc); break;
                default: accum<6>(xB, yB, acc); break;
            }
        }
    }

    // ---- stores: 7 d x 8 w per thread ----
    if (lane < 26) {
        const int wg = W0 + 8 * lane;
#pragma unroll
        for (int i = 0; i < 7; i++) {
            const int d = 7 * wid + i;
            float* o = out + (((long)b * D_DIM + d) * H_DIM + h) * W_DIM + wg;
            float2 p0 = upk(acc[i * 4 + 0]);
            float2 p1 = upk(acc[i * 4 + 1]);
            float2 p2 = upk(acc[i * 4 + 2]);
            float2 p3 = upk(acc[i * 4 + 3]);
            *reinterpret_cast<float4*>(o) = make_float4(p0.x, p0.y, p1.x, p1.y);
            *reinterpret_cast<float4*>(o + 4) = make_float4(p2.x, p2.y, p3.x, p3.y);
        }
    }
}

extern "C" void kernel_launch(void* const* d_in, const int* in_sizes, int n_in,
                              void* d_out, int out_size) {
    const float* x = (const float*)d_in[0];
    const float* y = (const float*)d_in[1];
    float* out = (float*)d_out;

    cudaFuncSetAttribute(coex_cost_kernel,
                         cudaFuncAttributeMaxDynamicSharedMemorySize, SMEM_BYTES);

    coex_cost_kernel<<<2 * B_DIM * H_DIM, NTHREADS, SMEM_BYTES>>>(x, y, out);
}

// round 6
// speedup vs baseline: 1.1422x; 1.1422x over previous
#include <cuda_runtime.h>

// CoExCostVolume: cost[b,d,h,w] = sum_c x[b,c,h,w]*y[b,c,h,w-d], zero for w<d.
// B=8, C=96, H=128, W=416, D=49.
//
// Grid 2048 = (b, h, half-row of 208 w). 224 threads = 7 warps; warp wid owns
// disparities [7*wid, 7*wid+7), lane L (<26) owns w in [8L, 8L+8).
// Warp-uniform d0 => all smem load offsets are compile-time immediates.
// x: +2/8 skew, LDS.64 conflict-free; y: +1/8 skew, scalar LDS conflict-free.
// cp.async 4-buffer pipeline (depth 3), 12 chunks of 8 channels.
// 2 CTAs/SM (70KB smem each, ~130 regs, NO spills — R5's 3-CTA cap spilled).

#define B_DIM 8
#define C_DIM 96
#define H_DIM 128
#define W_DIM 416
#define D_DIM 49
#define HW (H_DIM * W_DIM)
#define HALFW 208

#define CC 8
#define NC 12
#define NBUF 4
#define XSTRIDE 260           // >= sidxx(207)+1 = 258, even
#define YSTRIDE 288           // >= 9*25 + SY(55)+1 = 287, even
#define XSZ (CC * XSTRIDE)    // 2080
#define YSZ (CC * YSTRIDE)    // 2304
#define BUFSZ (XSZ + YSZ)     // 4384 floats
#define NTHREADS 224
#define SMEM_BYTES (NBUF * BUFSZ * 4)   // 70144

typedef unsigned long long ull;

__host__ __device__ constexpr int SY(int p) { return p + (p >> 3); }        // +1/8
__device__ __forceinline__ int sidxx(int p) { return p + ((p >> 3) << 1); } // +2/8

__device__ __forceinline__ void cp8(float* dst_smem, const float* src) {
    unsigned s = (unsigned)__cvta_generic_to_shared(dst_smem);
    asm volatile("cp.async.ca.shared.global [%0], [%1], 8;\n" ::"r"(s), "l"(src));
}
__device__ __forceinline__ void cp4(float* dst_smem, const float* src) {
    unsigned s = (unsigned)__cvta_generic_to_shared(dst_smem);
    asm volatile("cp.async.ca.shared.global [%0], [%1], 4;\n" ::"r"(s), "l"(src));
}
__device__ __forceinline__ ull pk(float lo, float hi) {
    ull r; asm("mov.b64 %0, {%1, %2};" : "=l"(r) : "f"(lo), "f"(hi)); return r;
}
__device__ __forceinline__ void fma2(ull& d, ull a, ull b) {
    asm("fma.rn.f32x2 %0, %1, %2, %0;" : "+l"(d) : "l"(a), "l"(b));
}
__device__ __forceinline__ float2 upk(ull p) {
    float2 v; asm("mov.b64 {%0, %1}, %2;" : "=f"(v.x), "=f"(v.y) : "l"(p)); return v;
}

// Warp-specialized accumulation over one 8-channel chunk; all offsets immediate.
// xB = xs + 10*L, yB = ys + 9*L.
template <int W>
__device__ __forceinline__ void accum(const float* __restrict__ xB,
                                      const float* __restrict__ yB,
                                      ull* __restrict__ acc) {
    constexpr int Q = 42 - 7 * W;  // y window base (coord minus 8L), >= 0
#pragma unroll 4
    for (int c = 0; c < CC; c++) {
        const float* xr = xB + c * XSTRIDE;
        const float* yr = yB + c * YSTRIDE;
        float2 xp[4];
#pragma unroll
        for (int j = 0; j < 4; j++)
            xp[j] = *reinterpret_cast<const float2*>(xr + 2 * j);
        float yv[14];
#pragma unroll
        for (int t = 0; t < 14; t++) yv[t] = yr[SY(Q + t)];

        ull px[4];
#pragma unroll
        for (int j = 0; j < 4; j++) px[j] = pk(xp[j].x, xp[j].y);
        ull py[13];
#pragma unroll
        for (int t = 0; t < 13; t++) py[t] = pk(yv[t], yv[t + 1]);

#pragma unroll
        for (int i = 0; i < 7; i++)
#pragma unroll
            for (int j = 0; j < 4; j++)
                fma2(acc[i * 4 + j], px[j], py[2 * j + 6 - i]);
    }
}

__global__ void __launch_bounds__(NTHREADS, 2)
coex_cost_kernel(const float* __restrict__ x,
                 const float* __restrict__ y,
                 float* __restrict__ out) {
    extern __shared__ float sm[];

    const int bid = blockIdx.x;
    const int half = bid & 1;
    const int h = (bid >> 1) & 127;
    const int b = bid >> 8;
    const int W0 = half * HALFW;

    const int tid = threadIdx.x;
    const int wid = tid >> 5;        // 0..6 (warp-uniform d-group)
    const int lane = tid & 31;       // 0..25 active for compute/stores

    const long rowb = ((long)(b * C_DIM) * H_DIM + h) * W_DIM;
    const long gx = rowb + W0;
    const long gy = rowb + W0 - 48;   // y coord p in [0,256)
    const int pmin = half ? 0 : 48;   // p<48 is zero pad for half 0

    // ---- zero y left-pad (half 0 only), all buffers, once ----
    if (half == 0) {
        for (int i = tid; i < NBUF * CC * 48; i += NTHREADS) {
            int buf = i / (CC * 48);
            int r = i - buf * (CC * 48);
            int c = r / 48;
            int p = r - c * 48;
            sm[buf * BUFSZ + XSZ + c * YSTRIDE + SY(p)] = 0.0f;
        }
    }

    auto stage = [&](int k) {
        const long co = (long)k * CC * HW;
        float* xs = sm + (k & (NBUF - 1)) * BUFSZ;
        float* ys = xs + XSZ;
#pragma unroll 1
        for (int idx = tid; idx < CC * 104; idx += NTHREADS) {
            int c = idx / 104;
            int w = (idx - c * 104) * 2;
            cp8(xs + c * XSTRIDE + sidxx(w), x + gx + co + (long)c * HW + w);
        }
#pragma unroll 1
        for (int idx = tid; idx < CC * 256; idx += NTHREADS) {
            int c = idx >> 8;
            int p = idx & 255;
            if (p >= pmin)
                cp4(ys + c * YSTRIDE + SY(p), y + gy + co + (long)c * HW + p);
        }
    };

    ull acc[28];
#pragma unroll
    for (int i = 0; i < 28; i++) acc[i] = 0ull;

    const int xboff = 10 * lane;      // sidxx(8*lane)
    const int yboff = 9 * lane;       // skew part of SY(8*lane + q)

    stage(0); asm volatile("cp.async.commit_group;\n");
    stage(1); asm volatile("cp.async.commit_group;\n");
    stage(2); asm volatile("cp.async.commit_group;\n");

#pragma unroll 1
    for (int k = 0; k < NC; k++) {
        if (k < NC - 2)       asm volatile("cp.async.wait_group 2;\n" ::: "memory");
        else if (k == NC - 2) asm volatile("cp.async.wait_group 1;\n" ::: "memory");
        else                  asm volatile("cp.async.wait_group 0;\n" ::: "memory");
        __syncthreads();

        if (k + 3 < NC) {
            stage(k + 3);
            asm volatile("cp.async.commit_group;\n");
        }

        const float* buf = sm + (k & (NBUF - 1)) * BUFSZ;
        const float* xB = buf + xboff;
        const float* yB = buf + XSZ + yboff;
        if (lane < 26) {
            switch (wid) {
                case 0: accum<0>(xB, yB, acc); break;
                case 1: accum<1>(xB, yB, acc); break;
                case 2: accum<2>(xB, yB, acc); break;
                case 3: accum<3>(xB, yB, acc); break;
                case 4: accum<4>(xB, yB, acc); break;
                case 5: accum<5>(xB, yB, acc); break;
                default: accum<6>(xB, yB, acc); break;
            }
        }
    }

    // ---- stores: 7 d x 8 w per thread ----
    if (lane < 26) {
        const int wg = W0 + 8 * lane;
#pragma unroll
        for (int i = 0; i < 7; i++) {
            const int d = 7 * wid + i;
            float* o = out + (((long)b * D_DIM + d) * H_DIM + h) * W_DIM + wg;
            float2 p0 = upk(acc[i * 4 + 0]);
            float2 p1 = upk(acc[i * 4 + 1]);
            float2 p2 = upk(acc[i * 4 + 2]);
            float2 p3 = upk(acc[i * 4 + 3]);
            *reinterpret_cast<float4*>(o) = make_float4(p0.x, p0.y, p1.x, p1.y);
            *reinterpret_cast<float4*>(o + 4) = make_float4(p2.x, p2.y, p3.x, p3.y);
        }
    }
}

extern "C" void kernel_launch(void* const* d_in, const int* in_sizes, int n_in,
                              void* d_out, int out_size) {
    const float* x = (const float*)d_in[0];
    const float* y = (const float*)d_in[1];
    float* out = (float*)d_out;

    cudaFuncSetAttribute(coex_cost_kernel,
                         cudaFuncAttributeMaxDynamicSharedMemorySize, SMEM_BYTES);

    coex_cost_kernel<<<2 * B_DIM * H_DIM, NTHREADS, SMEM_BYTES>>>(x, y, out);
}

// round 7
// speedup vs baseline: 2.4374x; 2.1340x over previous
#include <cuda_runtime.h>

// CoExCostVolume: cost[b,d,h,w] = sum_c x[b,c,h,w]*y[b,c,h,w-d], zero for w<d.
// B=8, C=96, H=128, W=416, D=49.
//
// One CTA per (b,h) row, 448 threads = 7 warp-pairs; pair g owns d in
// [7g,7g+7), lane index l=(wid&1)*32+lane (<52 active) owns w in [8l,8l+8).
// Smem layout uses XOR swizzle S(p)=p^((p>>3)&4): keeps 16B alignment and is
// conflict-free for lane-stride-8-float LDS.128 at any 4-aligned phase.
// All compute loads are LDS.128 with immediate channel offsets (no inner ALU).
// cp.async(8B) 3-buffer depth-2 pipeline over 6 chunks of 16 channels.

#define B_DIM 8
#define C_DIM 96
#define H_DIM 128
#define W_DIM 416
#define D_DIM 49
#define HW (H_DIM * W_DIM)

#define CC 16
#define NC 6
#define NBUF 3
#define XSTRIDE 448            // >= max S(415)+1, mult of 32
#define YSTRIDE 480            // >= max S(463)+1, mult of 32
#define XSZ (CC * XSTRIDE)     // 7168
#define YSZ (CC * YSTRIDE)     // 7680
#define BUFSZ (XSZ + YSZ)      // 14848 floats
#define NTHREADS 448
#define SMEM_BYTES (NBUF * BUFSZ * 4)   // 178176

typedef unsigned long long ull;

__device__ __forceinline__ int SW(int p) { return p ^ ((p >> 3) & 4); }

__device__ __forceinline__ void cp8(float* dst_smem, const float* src) {
    unsigned s = (unsigned)__cvta_generic_to_shared(dst_smem);
    asm volatile("cp.async.ca.shared.global [%0], [%1], 8;\n" ::"r"(s), "l"(src));
}
__device__ __forceinline__ ull pk(float lo, float hi) {
    ull r; asm("mov.b64 %0, {%1, %2};" : "=l"(r) : "f"(lo), "f"(hi)); return r;
}
__device__ __forceinline__ void fma2(ull& d, ull a, ull b) {
    asm("fma.rn.f32x2 %0, %1, %2, %0;" : "+l"(d) : "l"(a), "l"(b));
}
__device__ __forceinline__ float2 upk(ull p) {
    float2 v; asm("mov.b64 {%0, %1}, %2;" : "=f"(v.x), "=f"(v.y) : "l"(p)); return v;
}

// One 16-channel chunk. R = window misalignment (warp-uniform). xo0/xo1/yo[]
// are swizzled in-buffer float offsets; channel stride is an immediate.
template <int R>
__device__ __forceinline__ void accum(const float* __restrict__ buf,
                                      int xo0, int xo1,
                                      const int* __restrict__ yo,
                                      ull* __restrict__ acc) {
    constexpr int NV = (R == 3) ? 5 : 4;
#pragma unroll 4
    for (int c = 0; c < CC; c++) {
        float4 x0 = *reinterpret_cast<const float4*>(buf + xo0 + c * XSTRIDE);
        float4 x1 = *reinterpret_cast<const float4*>(buf + xo1 + c * XSTRIDE);
        float yw[4 * NV];
#pragma unroll
        for (int v = 0; v < NV; v++) {
            float4 q = *reinterpret_cast<const float4*>(buf + yo[v] + c * YSTRIDE);
            yw[4 * v + 0] = q.x; yw[4 * v + 1] = q.y;
            yw[4 * v + 2] = q.z; yw[4 * v + 3] = q.w;
        }
        ull px[4];
        px[0] = pk(x0.x, x0.y); px[1] = pk(x0.z, x0.w);
        px[2] = pk(x1.x, x1.y); px[3] = pk(x1.z, x1.w);
        ull py[13];
#pragma unroll
        for (int t = 0; t < 13; t++) py[t] = pk(yw[R + t], yw[R + t + 1]);
#pragma unroll
        for (int i = 0; i < 7; i++)
#pragma unroll
            for (int j = 0; j < 4; j++)
                fma2(acc[i * 4 + j], px[j], py[2 * j + 6 - i]);
    }
}

__global__ void __launch_bounds__(NTHREADS, 1)
coex_cost_kernel(const float* __restrict__ x,
                 const float* __restrict__ y,
                 float* __restrict__ out) {
    extern __shared__ float sm[];

    const int bid = blockIdx.x;
    const int b = bid >> 7;
    const int h = bid & 127;
    const int tid = threadIdx.x;
    const int wid = tid >> 5;
    const int lane = tid & 31;
    const int g = wid >> 1;                       // 0..6 d-group (warp-uniform)
    const int l = ((wid & 1) << 5) + lane;        // 0..63
    const bool active = (l < 52);
    const int d0 = 7 * g;
    const int w0 = 8 * l;

    const long rowb = ((long)(b * C_DIM) * H_DIM + h) * W_DIM;

    // ---- zero y left-pad once (all buffers); S is a bijection on [0,48) ----
    for (int i = tid; i < NBUF * CC * 48; i += NTHREADS) {
        int buf = i / (CC * 48);
        int rest = i - buf * (CC * 48);
        int c = rest / 48;
        int p = rest - c * 48;
        sm[buf * BUFSZ + XSZ + c * YSTRIDE + p] = 0.0f;
    }

    // ---- per-thread vector addresses (in-buffer offsets) ----
    const int r = (2 + g) & 3;                    // warp-uniform
    const int Qa = w0 + 42 - d0 - r;              // 4-aligned window start
    const int xo0 = SW(w0);
    const int xo1 = SW(w0 + 4);
    int yo[5];
#pragma unroll
    for (int v = 0; v < 5; v++) yo[v] = XSZ + SW(Qa + 4 * v);

    ull acc[28];
#pragma unroll
    for (int i = 0; i < 28; i++) acc[i] = 0ull;

    // ---- staging: 8B cp.async; x and y rows interleaved per index ----
    auto stage = [&](int k) {
        const long co = rowb + (long)k * CC * HW;
        float* xs = sm + (k % NBUF) * BUFSZ;
        float* ys = xs + XSZ;
#pragma unroll 1
        for (int idx = tid; idx < CC * 208; idx += NTHREADS) {
            int c = idx / 208;
            int p = (idx - c * 208) * 2;
            const long gsrc = co + (long)c * HW + p;
            cp8(xs + c * XSTRIDE + SW(p), x + gsrc);
            cp8(ys + c * YSTRIDE + SW(48 + p), y + gsrc);
        }
    };

    stage(0); asm volatile("cp.async.commit_group;\n");
    stage(1); asm volatile("cp.async.commit_group;\n");

#pragma unroll 1
    for (int k = 0; k < NC; k++) {
        if (k < NC - 1) asm volatile("cp.async.wait_group 1;\n" ::: "memory");
        else            asm volatile("cp.async.wait_group 0;\n" ::: "memory");
        __syncthreads();

        if (k + 2 < NC) {
            stage(k + 2);
            asm volatile("cp.async.commit_group;\n");
        }

        const float* buf = sm + (k % NBUF) * BUFSZ;
        if (active) {
            switch (r) {
                case 0: accum<0>(buf, xo0, xo1, yo, acc); break;
                case 1: accum<1>(buf, xo0, xo1, yo, acc); break;
                case 2: accum<2>(buf, xo0, xo1, yo, acc); break;
                default: accum<3>(buf, xo0, xo1, yo, acc); break;
            }
        }
    }

    // ---- stores: 7 d x 8 w per active thread ----
    if (active) {
#pragma unroll
        for (int i = 0; i < 7; i++) {
            const int d = d0 + i;
            float* o = out + (((long)b * D_DIM + d) * H_DIM + h) * W_DIM + w0;
            float2 p0 = upk(acc[i * 4 + 0]);
            float2 p1 = upk(acc[i * 4 + 1]);
            float2 p2 = upk(acc[i * 4 + 2]);
            float2 p3 = upk(acc[i * 4 + 3]);
            *reinterpret_cast<float4*>(o) = make_float4(p0.x, p0.y, p1.x, p1.y);
            *reinterpret_cast<float4*>(o + 4) = make_float4(p2.x, p2.y, p3.x, p3.y);
        }
    }
}

extern "C" void kernel_launch(void* const* d_in, const int* in_sizes, int n_in,
                              void* d_out, int out_size) {
    const float* x = (const float*)d_in[0];
    const float* y = (const float*)d_in[1];
    float* out = (float*)d_out;

    cudaFuncSetAttribute(coex_cost_kernel,
                         cudaFuncAttributeMaxDynamicSharedMemorySize, SMEM_BYTES);

    coex_cost_kernel<<<B_DIM * H_DIM, NTHREADS, SMEM_BYTES>>>(x, y, out);
}